// round 3
// baseline (speedup 1.0000x reference)
#include <cuda_runtime.h>

#define NL     32
#define NF     720
#define NSUB   60
#define DTF    60.0f
#define CHUNK  32
#define NCHUNK 23            // ceil(719 / 32); last chunk has 15 steps

// Persistent scratch (__device__ globals per allocation rules)
__device__ float2 g_P [NL * NL];        // P = M^60, row-major
__device__ float2 g_g0[NL];             // response to tau_k
__device__ float2 g_g1[NL];             // response to tau_{k+1}
__device__ float2 g_PL[NL * NL];        // P^CHUNK, row-major
__device__ float2 g_D [NCHUNK - 1][NL]; // chunk inhomogeneous sums (c=0..21)
__device__ float2 g_C [NCHUNK][NL];     // carries w_{CHUNK*c}

// ---------------------------------------------------------------------------
// Warp-wide dense complex matvec: w <- P*w + (fr, fi). Lane = row.
// Prow: this lane's row of P in registers.
// ---------------------------------------------------------------------------
__device__ __forceinline__ void pmatvec(const float2* __restrict__ Prow,
                                        float& wr, float& wi,
                                        float fr, float fi)
{
    const unsigned FULL = 0xffffffffu;
    float ar0 = fr,  ai0 = fi;
    float ar1 = 0.f, ai1 = 0.f;
    float ar2 = 0.f, ai2 = 0.f;
    float ar3 = 0.f, ai3 = 0.f;

    #pragma unroll
    for (int j = 0; j < NL; j += 4) {
        float br0 = __shfl_sync(FULL, wr, j + 0);
        float bi0 = __shfl_sync(FULL, wi, j + 0);
        float br1 = __shfl_sync(FULL, wr, j + 1);
        float bi1 = __shfl_sync(FULL, wi, j + 1);
        float br2 = __shfl_sync(FULL, wr, j + 2);
        float bi2 = __shfl_sync(FULL, wi, j + 2);
        float br3 = __shfl_sync(FULL, wr, j + 3);
        float bi3 = __shfl_sync(FULL, wi, j + 3);

        ar0 = fmaf(Prow[j+0].x, br0, ar0); ar0 = fmaf(-Prow[j+0].y, bi0, ar0);
        ai0 = fmaf(Prow[j+0].x, bi0, ai0); ai0 = fmaf( Prow[j+0].y, br0, ai0);
        ar1 = fmaf(Prow[j+1].x, br1, ar1); ar1 = fmaf(-Prow[j+1].y, bi1, ar1);
        ai1 = fmaf(Prow[j+1].x, bi1, ai1); ai1 = fmaf( Prow[j+1].y, br1, ai1);
        ar2 = fmaf(Prow[j+2].x, br2, ar2); ar2 = fmaf(-Prow[j+2].y, bi2, ar2);
        ai2 = fmaf(Prow[j+2].x, bi2, ai2); ai2 = fmaf( Prow[j+2].y, br2, ai2);
        ar3 = fmaf(Prow[j+3].x, br3, ar3); ar3 = fmaf(-Prow[j+3].y, bi3, ar3);
        ai3 = fmaf(Prow[j+3].x, bi3, ai3); ai3 = fmaf( Prow[j+3].y, br3, ai3);
    }
    wr = (ar0 + ar1) + (ar2 + ar3);
    wi = (ai0 + ai1) + (ai2 + ai3);
}

// ---------------------------------------------------------------------------
// Kernel 1: setup in fp64. Warp c computes column c of P = M^60;
// warp 0 additionally computes g0, g1.
// ---------------------------------------------------------------------------
__global__ void __launch_bounds__(1024, 1)
setup_kernel(const float* __restrict__ pk, const float* __restrict__ fc)
{
    const unsigned FULL = 0xffffffffu;
    const int lane = threadIdx.x & 31;
    const int warp = threadIdx.x >> 5;

    const double kin  = exp((double)pk[2 * lane]);
    const double kout = exp((double)pk[2 * lane + 1]);
    const double dtf  = (double)DTF * (double)fc[0];

    const double ca  = (lane > 0)      ? (double)DTF * kin  : 0.0;
    const double cb  = (lane < NL - 1) ? (double)DTF * kout : 0.0;
    const double cmr = 1.0 - (double)DTF * (((lane > 0) ? kin : 0.0) + kout);

    // column `warp` of M^60
    double xr = (lane == warp) ? 1.0 : 0.0;
    double xi = 0.0;
    for (int s = 0; s < NSUB; ++s) {
        double xr_up = __shfl_up_sync  (FULL, xr, 1);
        double xi_up = __shfl_up_sync  (FULL, xi, 1);
        double xr_dn = __shfl_down_sync(FULL, xr, 1);
        double xi_dn = __shfl_down_sync(FULL, xi, 1);
        double yr = cmr * xr + dtf * xi + ca * xr_up + cb * xr_dn;
        double yi = cmr * xi - dtf * xr + ca * xi_up + cb * xi_dn;
        xr = yr; xi = yi;
    }
    g_P[lane * NL + warp] = make_float2((float)xr, (float)xi);

    if (warp == 0) {
        const double scale = (double)DTF * exp((double)pk[0]);
        double y0r = 0., y0i = 0., y1r = 0., y1i = 0.;
        for (int j = 0; j < NSUB; ++j) {
            double a0r = __shfl_up_sync  (FULL, y0r, 1);
            double a0i = __shfl_up_sync  (FULL, y0i, 1);
            double a1r = __shfl_up_sync  (FULL, y1r, 1);
            double a1i = __shfl_up_sync  (FULL, y1i, 1);
            double b0r = __shfl_down_sync(FULL, y0r, 1);
            double b0i = __shfl_down_sync(FULL, y0i, 1);
            double b1r = __shfl_down_sync(FULL, y1r, 1);
            double b1i = __shfl_down_sync(FULL, y1i, 1);

            double n0r = cmr * y0r + dtf * y0i + ca * a0r + cb * b0r;
            double n0i = cmr * y0i - dtf * y0r + ca * a0i + cb * b0i;
            double n1r = cmr * y1r + dtf * y1i + ca * a1r + cb * b1r;
            double n1i = cmr * y1i - dtf * y1r + ca * a1i + cb * b1i;

            const double aa = (double)j / (double)NSUB;
            if (lane == 0) {
                n0r += scale * (1.0 - aa);
                n1r += scale * aa;
            }
            y0r = n0r; y0i = n0i; y1r = n1r; y1i = n1i;
        }
        g_g0[lane] = make_float2((float)y0r, (float)y0i);
        g_g1[lane] = make_float2((float)y1r, (float)y1i);
    }
}

// ---------------------------------------------------------------------------
// Kernel 2: parallel phase A.
//   blocks 0..31  : column b of P^CHUNK via 32 homogeneous matvecs
//   blocks 32..53 : chunk sum D_c (32 forced matvecs from zero state)
// ---------------------------------------------------------------------------
__global__ void __launch_bounds__(32, 1)
phaseA_kernel(const float* __restrict__ TAx, const float* __restrict__ TAy)
{
    const int lane = threadIdx.x;
    const int b    = blockIdx.x;

    float2 Prow[NL];
    #pragma unroll
    for (int j = 0; j < NL; ++j) Prow[j] = g_P[lane * NL + j];

    if (b < NL) {
        // column b of P^CHUNK
        float wr = (lane == b) ? 1.0f : 0.0f;
        float wi = 0.0f;
        for (int m = 0; m < CHUNK; ++m)
            pmatvec(Prow, wr, wi, 0.0f, 0.0f);
        g_PL[lane * NL + b] = make_float2(wr, wi);
    } else {
        const int c = b - NL;                 // 0..21
        const float2 g0 = g_g0[lane];
        const float2 g1 = g_g1[lane];
        float wr = 0.0f, wi = 0.0f;
        float tax1 = TAx[c * CHUNK], tay1 = TAy[c * CHUNK];
        for (int m = 0; m < CHUNK; ++m) {
            const int k = c * CHUNK + m;
            const float tax0 = tax1, tay0 = tay1;
            tax1 = TAx[k + 1];
            tay1 = TAy[k + 1];
            float fr = tax0 * g0.x - tay0 * g0.y + tax1 * g1.x - tay1 * g1.y;
            float fi = tax0 * g0.y + tay0 * g0.x + tax1 * g1.y + tay1 * g1.x;
            pmatvec(Prow, wr, wi, fr, fi);
        }
        g_D[c][lane] = make_float2(wr, wi);
    }
}

// ---------------------------------------------------------------------------
// Kernel 3: serial carry chain, one warp, 22 matvecs with P^CHUNK.
// ---------------------------------------------------------------------------
__global__ void __launch_bounds__(32, 1)
carry_kernel()
{
    const int lane = threadIdx.x;
    float2 PLrow[NL];
    #pragma unroll
    for (int j = 0; j < NL; ++j) PLrow[j] = g_PL[lane * NL + j];

    float wr = 0.0f, wi = 0.0f;
    g_C[0][lane] = make_float2(0.0f, 0.0f);
    for (int c = 0; c < NCHUNK - 1; ++c) {
        const float2 d = g_D[c][lane];
        pmatvec(PLrow, wr, wi, d.x, d.y);
        g_C[c + 1][lane] = make_float2(wr, wi);
    }
}

// ---------------------------------------------------------------------------
// Kernel 4: final outputs. Block c replays chunk c from its carry.
// ---------------------------------------------------------------------------
__global__ void __launch_bounds__(32, 1)
final_kernel(const float* __restrict__ TAx, const float* __restrict__ TAy,
             float* __restrict__ out)
{
    const int lane = threadIdx.x;
    const int c    = blockIdx.x;

    float2 Prow[NL];
    #pragma unroll
    for (int j = 0; j < NL; ++j) Prow[j] = g_P[lane * NL + j];
    const float2 g0 = g_g0[lane];
    const float2 g1 = g_g1[lane];

    if (c == 0) {                       // state row 0 is zeros
        out[lane]           = 0.0f;
        out[NF * NL + lane] = 0.0f;
    }

    float2 w0 = g_C[c][lane];
    float wr = w0.x, wi = w0.y;

    const int nsteps = min(CHUNK, (NF - 1) - c * CHUNK);   // 32, last chunk 15
    float tax1 = TAx[c * CHUNK], tay1 = TAy[c * CHUNK];

    for (int m = 0; m < nsteps; ++m) {
        const int k = c * CHUNK + m;          // global step index <= 718
        const float tax0 = tax1, tay0 = tay1;
        tax1 = TAx[k + 1];
        tay1 = TAy[k + 1];
        float fr = tax0 * g0.x - tay0 * g0.y + tax1 * g1.x - tay1 * g1.y;
        float fi = tax0 * g0.y + tay0 * g0.x + tax1 * g1.y + tay1 * g1.x;
        pmatvec(Prow, wr, wi, fr, fi);

        out[(k + 1) * NL + lane]           = wr;   // U row k+1
        out[NF * NL + (k + 1) * NL + lane] = wi;   // V row k+1
    }
}

extern "C" void kernel_launch(void* const* d_in, const int* in_sizes, int n_in,
                              void* d_out, int out_size)
{
    const float* pk  = (const float*)d_in[0];
    const float* TAx = (const float*)d_in[1];
    const float* TAy = (const float*)d_in[2];
    const float* fc  = (const float*)d_in[3];
    float* out = (float*)d_out;

    setup_kernel<<<1, 1024>>>(pk, fc);
    phaseA_kernel<<<NL + (NCHUNK - 1), 32>>>(TAx, TAy);
    carry_kernel<<<1, 32>>>();
    final_kernel<<<NCHUNK, 32>>>(TAx, TAy, out);
}

// round 4
// speedup vs baseline: 6.3015x; 6.3015x over previous
#include <cuda_runtime.h>

#define NL     32
#define NF     720
#define NSUB   60
#define DTF    60.0f
#define CHUNK  20
#define NCHUNK 36            // ceil(719 / 20); last chunk has 19 steps

// Persistent scratch (__device__ globals per allocation rules)
__device__ float2 g_P [NL * NL];        // P = M^60, row-major
__device__ float2 g_g0[NL];             // response to tau_k
__device__ float2 g_g1[NL];             // response to tau_{k+1}
__device__ float2 g_PL[NL * NL];        // P^CHUNK, row-major
__device__ float2 g_D [NCHUNK - 1][NL]; // chunk inhomogeneous sums
__device__ float2 g_C [NCHUNK][NL];     // carries w_{CHUNK*c}

// ---------------------------------------------------------------------------
// Warp-wide dense complex matvec: w <- P*w + (fr, fi). Lane = row.
// ---------------------------------------------------------------------------
__device__ __forceinline__ void pmatvec(const float2* __restrict__ Prow,
                                        float& wr, float& wi,
                                        float fr, float fi)
{
    const unsigned FULL = 0xffffffffu;
    float ar0 = fr,  ai0 = fi;
    float ar1 = 0.f, ai1 = 0.f;
    float ar2 = 0.f, ai2 = 0.f;
    float ar3 = 0.f, ai3 = 0.f;

    #pragma unroll
    for (int j = 0; j < NL; j += 4) {
        float br0 = __shfl_sync(FULL, wr, j + 0);
        float bi0 = __shfl_sync(FULL, wi, j + 0);
        float br1 = __shfl_sync(FULL, wr, j + 1);
        float bi1 = __shfl_sync(FULL, wi, j + 1);
        float br2 = __shfl_sync(FULL, wr, j + 2);
        float bi2 = __shfl_sync(FULL, wi, j + 2);
        float br3 = __shfl_sync(FULL, wr, j + 3);
        float bi3 = __shfl_sync(FULL, wi, j + 3);

        ar0 = fmaf(Prow[j+0].x, br0, ar0); ar0 = fmaf(-Prow[j+0].y, bi0, ar0);
        ai0 = fmaf(Prow[j+0].x, bi0, ai0); ai0 = fmaf( Prow[j+0].y, br0, ai0);
        ar1 = fmaf(Prow[j+1].x, br1, ar1); ar1 = fmaf(-Prow[j+1].y, bi1, ar1);
        ai1 = fmaf(Prow[j+1].x, bi1, ai1); ai1 = fmaf( Prow[j+1].y, br1, ai1);
        ar2 = fmaf(Prow[j+2].x, br2, ar2); ar2 = fmaf(-Prow[j+2].y, bi2, ar2);
        ai2 = fmaf(Prow[j+2].x, bi2, ai2); ai2 = fmaf( Prow[j+2].y, br2, ai2);
        ar3 = fmaf(Prow[j+3].x, br3, ar3); ar3 = fmaf(-Prow[j+3].y, bi3, ar3);
        ai3 = fmaf(Prow[j+3].x, bi3, ai3); ai3 = fmaf( Prow[j+3].y, br3, ai3);
    }
    wr = (ar0 + ar1) + (ar2 + ar3);
    wi = (ai0 + ai1) + (ai2 + ai3);
}

// ---------------------------------------------------------------------------
// Kernel 1: setup (fp32 — fp64 is ~18 cyc/instr on B300 and cost 200 µs in R3).
// Warp c computes column c of P = M^60; warp 0 also computes g0, g1.
// ---------------------------------------------------------------------------
__global__ void __launch_bounds__(1024, 1)
setup_kernel(const float* __restrict__ pk, const float* __restrict__ fc)
{
    const unsigned FULL = 0xffffffffu;
    const int lane = threadIdx.x & 31;
    const int warp = threadIdx.x >> 5;

    const float kin  = expf(pk[2 * lane]);
    const float kout = expf(pk[2 * lane + 1]);
    const float dtf  = DTF * fc[0];

    const float ca  = (lane > 0)      ? DTF * kin  : 0.0f;
    const float cb  = (lane < NL - 1) ? DTF * kout : 0.0f;
    const float cmr = 1.0f - DTF * (((lane > 0) ? kin : 0.0f) + kout);

    float xr = (lane == warp) ? 1.0f : 0.0f;
    float xi = 0.0f;
    #pragma unroll 4
    for (int s = 0; s < NSUB; ++s) {
        float xr_up = __shfl_up_sync  (FULL, xr, 1);
        float xi_up = __shfl_up_sync  (FULL, xi, 1);
        float xr_dn = __shfl_down_sync(FULL, xr, 1);
        float xi_dn = __shfl_down_sync(FULL, xi, 1);
        float yr = cmr * xr + dtf * xi + ca * xr_up + cb * xr_dn;
        float yi = cmr * xi - dtf * xr + ca * xi_up + cb * xi_dn;
        xr = yr; xi = yi;
    }
    g_P[lane * NL + warp] = make_float2(xr, xi);

    if (warp == 0) {
        const float scale = DTF * expf(pk[0]);
        float y0r = 0.f, y0i = 0.f, y1r = 0.f, y1i = 0.f;
        for (int j = 0; j < NSUB; ++j) {
            float a0r = __shfl_up_sync  (FULL, y0r, 1);
            float a0i = __shfl_up_sync  (FULL, y0i, 1);
            float a1r = __shfl_up_sync  (FULL, y1r, 1);
            float a1i = __shfl_up_sync  (FULL, y1i, 1);
            float b0r = __shfl_down_sync(FULL, y0r, 1);
            float b0i = __shfl_down_sync(FULL, y0i, 1);
            float b1r = __shfl_down_sync(FULL, y1r, 1);
            float b1i = __shfl_down_sync(FULL, y1i, 1);

            float n0r = cmr * y0r + dtf * y0i + ca * a0r + cb * b0r;
            float n0i = cmr * y0i - dtf * y0r + ca * a0i + cb * b0i;
            float n1r = cmr * y1r + dtf * y1i + ca * a1r + cb * b1r;
            float n1i = cmr * y1i - dtf * y1r + ca * a1i + cb * b1i;

            const float aa = (float)j / (float)NSUB;
            if (lane == 0) {
                n0r += scale * (1.0f - aa);
                n1r += scale * aa;
            }
            y0r = n0r; y0i = n0i; y1r = n1r; y1i = n1i;
        }
        g_g0[lane] = make_float2(y0r, y0i);
        g_g1[lane] = make_float2(y1r, y1i);
    }
}

// ---------------------------------------------------------------------------
// Kernel 2: parallel phase A.
//   blocks 0..31       : column b of P^CHUNK
//   blocks 32..32+34   : chunk sum D_c (CHUNK forced matvecs from zero)
// ---------------------------------------------------------------------------
__global__ void __launch_bounds__(32, 1)
phaseA_kernel(const float* __restrict__ TAx, const float* __restrict__ TAy)
{
    const int lane = threadIdx.x;
    const int b    = blockIdx.x;

    float2 Prow[NL];
    #pragma unroll
    for (int j = 0; j < NL; ++j) Prow[j] = g_P[lane * NL + j];

    if (b < NL) {
        float wr = (lane == b) ? 1.0f : 0.0f;
        float wi = 0.0f;
        for (int m = 0; m < CHUNK; ++m)
            pmatvec(Prow, wr, wi, 0.0f, 0.0f);
        g_PL[lane * NL + b] = make_float2(wr, wi);
    } else {
        const int c = b - NL;                 // 0..NCHUNK-2
        const float2 g0 = g_g0[lane];
        const float2 g1 = g_g1[lane];
        float wr = 0.0f, wi = 0.0f;
        float tax1 = TAx[c * CHUNK], tay1 = TAy[c * CHUNK];
        for (int m = 0; m < CHUNK; ++m) {
            const int k = c * CHUNK + m;
            const float tax0 = tax1, tay0 = tay1;
            tax1 = TAx[k + 1];
            tay1 = TAy[k + 1];
            float fr = tax0 * g0.x - tay0 * g0.y + tax1 * g1.x - tay1 * g1.y;
            float fi = tax0 * g0.y + tay0 * g0.x + tax1 * g1.y + tay1 * g1.x;
            pmatvec(Prow, wr, wi, fr, fi);
        }
        g_D[c][lane] = make_float2(wr, wi);
    }
}

// ---------------------------------------------------------------------------
// Kernel 3: serial carry chain, one warp, NCHUNK-1 matvecs with P^CHUNK.
// ---------------------------------------------------------------------------
__global__ void __launch_bounds__(32, 1)
carry_kernel()
{
    const int lane = threadIdx.x;
    float2 PLrow[NL];
    #pragma unroll
    for (int j = 0; j < NL; ++j) PLrow[j] = g_PL[lane * NL + j];

    float wr = 0.0f, wi = 0.0f;
    g_C[0][lane] = make_float2(0.0f, 0.0f);
    for (int c = 0; c < NCHUNK - 1; ++c) {
        const float2 d = g_D[c][lane];
        pmatvec(PLrow, wr, wi, d.x, d.y);
        g_C[c + 1][lane] = make_float2(wr, wi);
    }
}

// ---------------------------------------------------------------------------
// Kernel 4: final outputs. Block c replays chunk c from its carry.
// ---------------------------------------------------------------------------
__global__ void __launch_bounds__(32, 1)
final_kernel(const float* __restrict__ TAx, const float* __restrict__ TAy,
             float* __restrict__ out)
{
    const int lane = threadIdx.x;
    const int c    = blockIdx.x;

    float2 Prow[NL];
    #pragma unroll
    for (int j = 0; j < NL; ++j) Prow[j] = g_P[lane * NL + j];
    const float2 g0 = g_g0[lane];
    const float2 g1 = g_g1[lane];

    if (c == 0) {
        out[lane]           = 0.0f;
        out[NF * NL + lane] = 0.0f;
    }

    float2 w0 = g_C[c][lane];
    float wr = w0.x, wi = w0.y;

    const int nsteps = min(CHUNK, (NF - 1) - c * CHUNK);
    float tax1 = TAx[c * CHUNK], tay1 = TAy[c * CHUNK];

    for (int m = 0; m < nsteps; ++m) {
        const int k = c * CHUNK + m;
        const float tax0 = tax1, tay0 = tay1;
        tax1 = TAx[k + 1];
        tay1 = TAy[k + 1];
        float fr = tax0 * g0.x - tay0 * g0.y + tax1 * g1.x - tay1 * g1.y;
        float fi = tax0 * g0.y + tay0 * g0.x + tax1 * g1.y + tay1 * g1.x;
        pmatvec(Prow, wr, wi, fr, fi);

        out[(k + 1) * NL + lane]           = wr;
        out[NF * NL + (k + 1) * NL + lane] = wi;
    }
}

extern "C" void kernel_launch(void* const* d_in, const int* in_sizes, int n_in,
                              void* d_out, int out_size)
{
    const float* pk  = (const float*)d_in[0];
    const float* TAx = (const float*)d_in[1];
    const float* TAy = (const float*)d_in[2];
    const float* fc  = (const float*)d_in[3];
    float* out = (float*)d_out;

    setup_kernel<<<1, 1024>>>(pk, fc);
    phaseA_kernel<<<NL + (NCHUNK - 1), 32>>>(TAx, TAy);
    carry_kernel<<<1, 32>>>();
    final_kernel<<<NCHUNK, 32>>>(TAx, TAy, out);
}